// round 14
// baseline (speedup 1.0000x reference)
#include <cuda_runtime.h>
#include <math.h>

#define B   2
#define L   2048
#define HID 1024
#define NH  16
#define E   128
#define HS  64
#define ML  (B*L)          // 4096
#define KD  1024           // inner dim of projections

// ---------------- scratch (static device globals; no allocs allowed) -------
__device__ float g_q[B*NH*L*E];     // (b,h,l,e)   32 MB
__device__ float g_k[B*NH*L*E];     // (b,h,l,e)   32 MB
__device__ float g_v[B*NH*L*HS];    // (b,h,l,d)   16 MB
__device__ float g_gu1[B*NH*L];     // gate_u_1 per (b,h,l)

// ============================================================================
// Projection GEMM: C(ML x N) = A(ML x 1024) @ W^T(N x 1024) (+ bias)
// Output scattered into (B,NH,L,EG) layout.  tgt: 0->g_q, 1->g_k, 2->g_v
// 64x64 block tile, BK=16, 256 threads, 4x4 microtile.
// ============================================================================
__global__ __launch_bounds__(256) void proj_kernel(
    const float* __restrict__ A,
    const float* __restrict__ W,
    const float* __restrict__ bias,   // may be null
    int EG, int tgt)
{
    __shared__ float As[16][68];   // [k][m]
    __shared__ float Ws[16][68];   // [k][n]

    const int tid = threadIdx.x;
    const int tx  = tid & 15;      // n micro
    const int ty  = tid >> 4;      // m micro
    const int m0  = blockIdx.y * 64;
    const int n0  = blockIdx.x * 64;

    const int lrow = tid >> 2;         // 0..63
    const int lkq  = (tid & 3) * 4;    // 0,4,8,12

    const float* Aptr = A + (size_t)(m0 + lrow) * KD + lkq;
    const float* Wptr = W + (size_t)(n0 + lrow) * KD + lkq;

    float c[4][4];
    #pragma unroll
    for (int i = 0; i < 4; i++)
        #pragma unroll
        for (int j = 0; j < 4; j++) c[i][j] = 0.f;

    for (int k0 = 0; k0 < KD; k0 += 16) {
        float4 a4 = *(const float4*)(Aptr + k0);
        float4 w4 = *(const float4*)(Wptr + k0);
        As[lkq+0][lrow] = a4.x; As[lkq+1][lrow] = a4.y;
        As[lkq+2][lrow] = a4.z; As[lkq+3][lrow] = a4.w;
        Ws[lkq+0][lrow] = w4.x; Ws[lkq+1][lrow] = w4.y;
        Ws[lkq+2][lrow] = w4.z; Ws[lkq+3][lrow] = w4.w;
        __syncthreads();

        #pragma unroll
        for (int kk = 0; kk < 16; kk++) {
            float4 av = *(const float4*)&As[kk][ty*4];
            float4 wv = *(const float4*)&Ws[kk][tx*4];
            const float* af = (const float*)&av;
            const float* wf = (const float*)&wv;
            #pragma unroll
            for (int i = 0; i < 4; i++)
                #pragma unroll
                for (int j = 0; j < 4; j++)
                    c[i][j] = fmaf(af[i], wf[j], c[i][j]);
        }
        __syncthreads();
    }

    float* out = (tgt == 0) ? g_q : (tgt == 1) ? g_k : g_v;

    #pragma unroll
    for (int i = 0; i < 4; i++) {
        const int mm = m0 + ty*4 + i;
        const int bb = mm / L;
        const int ll = mm % L;
        #pragma unroll
        for (int j = 0; j < 4; j++) {
            const int nn = n0 + tx*4 + j;
            const int h  = nn / EG;
            const int e  = nn % EG;
            float v = c[i][j];
            if (bias) v += bias[nn];
            out[(((size_t)bb*NH + h)*L + ll)*EG + e] = v;
        }
    }
}

// ============================================================================
// Gate: one warp per (b,h,l).
// g = sigmoid((q @ Wg^T + bg).reshape(...,2,4).sum(-1))
// gu1 = gu*(gr*eco - 1) + 2
// ============================================================================
__global__ __launch_bounds__(256) void gate_kernel(
    const float* __restrict__ Wg,   // (8,128)
    const float* __restrict__ bg,   // (8)
    const float* __restrict__ eco)  // (NH)
{
    const int gw   = (blockIdx.x * blockDim.x + threadIdx.x) >> 5;
    const int lane = threadIdx.x & 31;
    if (gw >= B*NH*L) return;

    const float* qrow = g_q + (size_t)gw * E;
    float qv[4];
    #pragma unroll
    for (int i = 0; i < 4; i++) qv[i] = qrow[lane + 32*i];

    float d[8];
    #pragma unroll
    for (int j = 0; j < 8; j++) {
        float s = 0.f;
        #pragma unroll
        for (int i = 0; i < 4; i++)
            s = fmaf(qv[i], __ldg(&Wg[j*E + lane + 32*i]), s);
        #pragma unroll
        for (int off = 16; off; off >>= 1)
            s += __shfl_xor_sync(0xffffffffu, s, off);
        d[j] = s;
    }
    if (lane == 0) {
        float su = d[0]+d[1]+d[2]+d[3] + bg[0]+bg[1]+bg[2]+bg[3];
        float sr = d[4]+d[5]+d[6]+d[7] + bg[4]+bg[5]+bg[6]+bg[7];
        float gu = 1.f / (1.f + expf(-su));
        float gr = 1.f / (1.f + expf(-sr));
        const int h = (gw / L) % NH;
        g_gu1[gw] = fmaf(gu, fmaf(gr, eco[h], -1.f), 2.f);
    }
}

// ============================================================================
// Flash attention with gated rel_pos bias.
// Block = (qtile, h, b). BM=BN=64, 256 threads, 4x4 microtiles.
// ============================================================================
#define BM 64
#define BN 64
#define QSTR 132   // E + 4 pad
#define VSTR 68    // HS + 4 pad
#define PSTR 68    // BN + 4 pad

__device__ __forceinline__ float dot4(float4 a, float4 b, float c) {
    return fmaf(a.x, b.x, fmaf(a.y, b.y, fmaf(a.z, b.z, fmaf(a.w, b.w, c))));
}

__global__ __launch_bounds__(256, 2) void attn_kernel(
    const float* __restrict__ mask,     // (B, L)
    const float* __restrict__ relpos,   // (NH, L, L)
    float* __restrict__ out)            // (B, L, HID)
{
    extern __shared__ float sm[];
    float* Qs  = sm;                    // [BM][QSTR]
    float* Ks  = Qs  + BM*QSTR;         // [BN][QSTR]
    float* Vs  = Ks  + BN*QSTR;         // [BN][VSTR]
    float* Ps  = Vs  + BN*VSTR;         // [BM][PSTR]  (P row-major)
    float* gur = Ps  + BM*PSTR;         // [BM]

    const int tid = threadIdx.x;
    const int tx  = tid & 15;
    const int ty  = tid >> 4;
    const int r0  = ty * 4;      // local query rows
    const int c0  = tx * 4;      // local key cols / out dims

    const int qt = blockIdx.x;
    const int h  = blockIdx.y;
    const int b  = blockIdx.z;
    const int lq0 = qt * BM;

    const size_t bh = (size_t)b*NH + h;
    const float* Qg = g_q + (bh*L + lq0) * E;
    const float* Kg = g_k + bh*L*E;
    const float* Vg = g_v + bh*L*HS;
    const float* relp = relpos + ((size_t)h*L + lq0) * L;

    // Q tile load (64x128 -> 2048 float4)
    for (int t = tid; t < BM*(E/4); t += 256) {
        const int r  = t >> 5;         // /32
        const int e4 = t & 31;
        *(float4*)(Qs + r*QSTR + e4*4) = *(const float4*)(Qg + r*E + e4*4);
    }
    if (tid < BM) gur[tid] = g_gu1[bh*L + lq0 + tid];

    float m_i[4], l_i[4], acc[4][4];
    #pragma unroll
    for (int i = 0; i < 4; i++) {
        m_i[i] = -1e30f; l_i[i] = 0.f;
        #pragma unroll
        for (int j = 0; j < 4; j++) acc[i][j] = 0.f;
    }

    for (int kt = 0; kt < L/BN; kt++) {
        const int kc0 = kt * BN;
        __syncthreads();   // prev PV / Q stores done before K,V overwrite

        for (int t = tid; t < BN*(E/4); t += 256) {
            const int r  = t >> 5;
            const int e4 = t & 31;
            *(float4*)(Ks + r*QSTR + e4*4) =
                *(const float4*)(Kg + (size_t)(kc0 + r)*E + e4*4);
        }
        for (int t = tid; t < BN*(HS/4); t += 256) {
            const int r  = t >> 4;
            const int d4 = t & 15;
            *(float4*)(Vs + r*VSTR + d4*4) =
                *(const float4*)(Vg + (size_t)(kc0 + r)*HS + d4*4);
        }
        __syncthreads();

        // ---- S = Q K^T ----
        float s[4][4];
        #pragma unroll
        for (int i = 0; i < 4; i++)
            #pragma unroll
            for (int j = 0; j < 4; j++) s[i][j] = 0.f;

        #pragma unroll 8
        for (int e4 = 0; e4 < 32; e4++) {
            float4 a[4], k4[4];
            #pragma unroll
            for (int i = 0; i < 4; i++)
                a[i]  = *(const float4*)(Qs + (r0+i)*QSTR + e4*4);
            #pragma unroll
            for (int j = 0; j < 4; j++)
                k4[j] = *(const float4*)(Ks + (c0+j)*QSTR + e4*4);
            #pragma unroll
            for (int i = 0; i < 4; i++)
                #pragma unroll
                for (int j = 0; j < 4; j++)
                    s[i][j] = dot4(a[i], k4[j], s[i][j]);
        }

        // ---- scale + mask + gated rel_pos ----
        const float4 mk = *(const float4*)(mask + (size_t)b*L + kc0 + c0);
        const float* mkf = (const float*)&mk;
        #pragma unroll
        for (int i = 0; i < 4; i++) {
            const float gi = gur[r0 + i];
            const float4 rp = *(const float4*)(relp + (size_t)(r0+i)*L + kc0 + c0);
            const float* rpf = (const float*)&rp;
            #pragma unroll
            for (int j = 0; j < 4; j++)
                s[i][j] = fmaf(s[i][j], 0.125f, mkf[j] + gi * rpf[j]);
        }

        // ---- online softmax (reduce over 16-lane row groups) ----
        #pragma unroll
        for (int i = 0; i < 4; i++) {
            float mt = fmaxf(fmaxf(s[i][0], s[i][1]), fmaxf(s[i][2], s[i][3]));
            #pragma unroll
            for (int off = 1; off < 16; off <<= 1)
                mt = fmaxf(mt, __shfl_xor_sync(0xffffffffu, mt, off));
            const float mnew = fmaxf(m_i[i], mt);
            const float corr = __expf(m_i[i] - mnew);
            m_i[i] = mnew;
            float rs = 0.f;
            #pragma unroll
            for (int j = 0; j < 4; j++) {
                s[i][j] = __expf(s[i][j] - mnew);
                rs += s[i][j];
            }
            #pragma unroll
            for (int off = 1; off < 16; off <<= 1)
                rs += __shfl_xor_sync(0xffffffffu, rs, off);
            l_i[i] = l_i[i] * corr + rs;
            #pragma unroll
            for (int j = 0; j < 4; j++) {
                acc[i][j] *= corr;
                Ps[(r0+i)*PSTR + c0 + j] = s[i][j];
            }
        }
        __syncthreads();

        // ---- acc += P @ V ----
        #pragma unroll 4
        for (int c4 = 0; c4 < 16; c4++) {
            float4 p4[4];
            #pragma unroll
            for (int i = 0; i < 4; i++)
                p4[i] = *(const float4*)(Ps + (r0+i)*PSTR + c4*4);
            #pragma unroll
            for (int cc = 0; cc < 4; cc++) {
                const float4 vv = *(const float4*)(Vs + (c4*4+cc)*VSTR + c0);
                const float* vf = (const float*)&vv;
                #pragma unroll
                for (int i = 0; i < 4; i++) {
                    const float p = ((const float*)&p4[i])[cc];
                    #pragma unroll
                    for (int j = 0; j < 4; j++)
                        acc[i][j] = fmaf(p, vf[j], acc[i][j]);
                }
            }
        }
    }

    // ---- epilogue ----
    #pragma unroll
    for (int i = 0; i < 4; i++) {
        const float inv = 1.f / l_i[i];
        float4 o;
        o.x = acc[i][0]*inv; o.y = acc[i][1]*inv;
        o.z = acc[i][2]*inv; o.w = acc[i][3]*inv;
        *(float4*)(out + ((size_t)b*L + lq0 + r0 + i)*HID + h*HS + c0) = o;
    }
}

// ============================================================================
extern "C" void kernel_launch(void* const* d_in, const int* in_sizes, int n_in,
                              void* d_out, int out_size) {
    const float* hs   = (const float*)d_in[0];
    const float* mask = (const float*)d_in[1];
    const float* rel  = (const float*)d_in[2];
    const float* Wq   = (const float*)d_in[3];
    const float* bq   = (const float*)d_in[4];
    const float* Wk   = (const float*)d_in[5];
    const float* Wv   = (const float*)d_in[6];
    const float* bv   = (const float*)d_in[7];
    const float* Wg   = (const float*)d_in[8];
    const float* bg   = (const float*)d_in[9];
    const float* eco  = (const float*)d_in[10];
    float* out = (float*)d_out;

    // projections: Q (N=2048, bias), K (N=2048, no bias), V (N=1024, bias)
    proj_kernel<<<dim3(2048/64, ML/64), 256>>>(hs, Wq, bq,  E,  0);
    proj_kernel<<<dim3(2048/64, ML/64), 256>>>(hs, Wk, nullptr, E, 1);
    proj_kernel<<<dim3(1024/64, ML/64), 256>>>(hs, Wv, bv,  HS, 2);

    // gates
    gate_kernel<<<(B*NH*L)/8, 256>>>(Wg, bg, eco);

    // attention
    const int smem_bytes = (BM*QSTR + BN*QSTR + BN*VSTR + BM*PSTR + BM) * sizeof(float);
    cudaFuncSetAttribute(attn_kernel,
                         cudaFuncAttributeMaxDynamicSharedMemorySize, smem_bytes);
    attn_kernel<<<dim3(L/BM, NH, B), 256, smem_bytes>>>(mask, rel, out);
}

// round 15
// speedup vs baseline: 3.7255x; 3.7255x over previous
#include <cuda_runtime.h>
#include <math.h>

#define B   2
#define L   2048
#define HID 1024
#define NH  16
#define E   128
#define HS  64
#define ML  (B*L)          // 4096
#define KD  1024           // inner dim of projections

// ---------------- scratch (static device globals; no allocs allowed) -------
__device__ float g_q[B*NH*L*E];     // (b,h,l,e)
__device__ float g_k[B*NH*L*E];     // (b,h,l,e)
__device__ float g_v[B*NH*L*HS];    // (b,h,l,d)
__device__ float g_gu1[B*NH*L];     // gate_u_1 per (b,h,l)

// ---------------- tf32 helpers ---------------------------------------------
__device__ __forceinline__ unsigned f2tf(float x) {
    unsigned u;
    asm("cvt.rna.tf32.f32 %0, %1;" : "=r"(u) : "f"(x));
    return u;
}

__device__ __forceinline__ void mma_tf32(float* d, const unsigned* a, const unsigned* b) {
    asm volatile(
        "mma.sync.aligned.m16n8k8.row.col.f32.tf32.tf32.f32 "
        "{%0,%1,%2,%3}, {%4,%5,%6,%7}, {%8,%9}, {%0,%1,%2,%3};\n"
        : "+f"(d[0]), "+f"(d[1]), "+f"(d[2]), "+f"(d[3])
        : "r"(a[0]), "r"(a[1]), "r"(a[2]), "r"(a[3]), "r"(b[0]), "r"(b[1]));
}

// ============================================================================
// Projection GEMM (tf32 tensor cores):
//   C(ML x N) = A(ML x 1024) @ W^T(N x 1024) (+ bias), scatter to (B,NH,L,EG)
// Block tile 128x128, BK=32, 128 threads = 4 warps, warp tile 64x64.
// ============================================================================
#define PSTR 36   // smem k-stride (banks: (4g+t) mod 32 distinct -> conflict-free)

__global__ __launch_bounds__(128, 2) void proj_kernel(
    const float* __restrict__ A,
    const float* __restrict__ W,
    const float* __restrict__ bias,   // may be null
    int EG, int tgt)
{
    __shared__ unsigned As[128 * PSTR];
    __shared__ unsigned Ws[128 * PSTR];

    const int tid  = threadIdx.x;
    const int wid  = tid >> 5;
    const int lane = tid & 31;
    const int g    = lane >> 2;   // 0..7
    const int t    = lane & 3;    // 0..3
    const int wm   = wid >> 1;    // 0..1
    const int wn   = wid & 1;     // 0..1

    const int m0 = blockIdx.y * 128;
    const int n0 = blockIdx.x * 128;

    float c[4][8][4];
    #pragma unroll
    for (int mt = 0; mt < 4; mt++)
        #pragma unroll
        for (int nt = 0; nt < 8; nt++)
            #pragma unroll
            for (int r = 0; r < 4; r++) c[mt][nt][r] = 0.f;

    for (int k0 = 0; k0 < KD; k0 += 32) {
        __syncthreads();
        // load A,W tiles (128x32 each), convert to tf32, store to smem
        #pragma unroll
        for (int i = 0; i < 8; i++) {
            const int f4  = tid + i * 128;
            const int row = f4 >> 3;
            const int c4  = f4 & 7;
            float4 a4 = *(const float4*)(A + (size_t)(m0 + row) * KD + k0 + c4 * 4);
            float4 w4 = *(const float4*)(W + (size_t)(n0 + row) * KD + k0 + c4 * 4);
            uint4 au = make_uint4(f2tf(a4.x), f2tf(a4.y), f2tf(a4.z), f2tf(a4.w));
            uint4 wu = make_uint4(f2tf(w4.x), f2tf(w4.y), f2tf(w4.z), f2tf(w4.w));
            *(uint4*)(As + row * PSTR + c4 * 4) = au;
            *(uint4*)(Ws + row * PSTR + c4 * 4) = wu;
        }
        __syncthreads();

        #pragma unroll
        for (int ks = 0; ks < 4; ks++) {
            unsigned af[4][4], bf[8][2];
            #pragma unroll
            for (int mt = 0; mt < 4; mt++) {
                const int r = (wm * 64 + mt * 16 + g) * PSTR + ks * 8 + t;
                af[mt][0] = As[r];
                af[mt][1] = As[r + 8 * PSTR];
                af[mt][2] = As[r + 4];
                af[mt][3] = As[r + 8 * PSTR + 4];
            }
            #pragma unroll
            for (int nt = 0; nt < 8; nt++) {
                const int r = (wn * 64 + nt * 8 + g) * PSTR + ks * 8 + t;
                bf[nt][0] = Ws[r];
                bf[nt][1] = Ws[r + 4];
            }
            #pragma unroll
            for (int mt = 0; mt < 4; mt++)
                #pragma unroll
                for (int nt = 0; nt < 8; nt++)
                    mma_tf32(c[mt][nt], af[mt], bf[nt]);
        }
    }

    float* out = (tgt == 0) ? g_q : (tgt == 1) ? g_k : g_v;

    #pragma unroll
    for (int mt = 0; mt < 4; mt++) {
        #pragma unroll
        for (int rr = 0; rr < 2; rr++) {            // rr=0: row g, rr=1: row g+8
            const int mrow = m0 + wm * 64 + mt * 16 + g + rr * 8;
            const int bb = mrow / L;
            const int ll = mrow % L;
            #pragma unroll
            for (int nt = 0; nt < 8; nt++) {
                const int nn = n0 + wn * 64 + nt * 8 + 2 * t;
                const int h  = nn / EG;
                const int e  = nn % EG;
                float v0 = c[mt][nt][rr * 2 + 0];
                float v1 = c[mt][nt][rr * 2 + 1];
                if (bias) { v0 += bias[nn]; v1 += bias[nn + 1]; }
                float2 o = make_float2(v0, v1);
                *(float2*)(out + (((size_t)bb * NH + h) * L + ll) * EG + e) = o;
            }
        }
    }
}

// ============================================================================
// Gate: one warp per (b,h,l).
// ============================================================================
__global__ __launch_bounds__(256) void gate_kernel(
    const float* __restrict__ Wg,   // (8,128)
    const float* __restrict__ bg,   // (8)
    const float* __restrict__ eco)  // (NH)
{
    const int gw   = (blockIdx.x * blockDim.x + threadIdx.x) >> 5;
    const int lane = threadIdx.x & 31;
    if (gw >= B*NH*L) return;

    const float* qrow = g_q + (size_t)gw * E;
    float qv[4];
    #pragma unroll
    for (int i = 0; i < 4; i++) qv[i] = qrow[lane + 32*i];

    float d[8];
    #pragma unroll
    for (int j = 0; j < 8; j++) {
        float s = 0.f;
        #pragma unroll
        for (int i = 0; i < 4; i++)
            s = fmaf(qv[i], __ldg(&Wg[j*E + lane + 32*i]), s);
        #pragma unroll
        for (int off = 16; off; off >>= 1)
            s += __shfl_xor_sync(0xffffffffu, s, off);
        d[j] = s;
    }
    if (lane == 0) {
        float su = d[0]+d[1]+d[2]+d[3] + bg[0]+bg[1]+bg[2]+bg[3];
        float sr = d[4]+d[5]+d[6]+d[7] + bg[4]+bg[5]+bg[6]+bg[7];
        float gu = 1.f / (1.f + expf(-su));
        float gr = 1.f / (1.f + expf(-sr));
        const int h = (gw / L) % NH;
        g_gu1[gw] = fmaf(gu, fmaf(gr, eco[h], -1.f), 2.f);
    }
}

// ============================================================================
// Flash attention (tf32 tensor cores) with gated rel_pos bias.
// Block = (qtile 64, h, b), 128 threads = 4 warps, each warp: 16 full rows.
// Q frags register-resident. K / V^T / P staged in smem as tf32.
// ============================================================================
#define KSTR 132   // K/Q smem k-stride  ((4g+t) mod 32 distinct)
#define VSTR 68    // V^T smem stride
#define PSTRD 68   // P  smem stride

__global__ __launch_bounds__(128, 2) void attn_kernel(
    const float* __restrict__ mask,     // (B, L)
    const float* __restrict__ relpos,   // (NH, L, L)
    float* __restrict__ out)            // (B, L, HID)
{
    extern __shared__ unsigned sm[];
    unsigned* Ks  = sm;                    // [64][KSTR]  (also Q staging)
    unsigned* VsT = Ks + 64 * KSTR;        // [HS][VSTR]  (V transposed: [d][kr])
    unsigned* Ps  = VsT + HS * VSTR;       // [4][16][PSTRD]

    const int tid  = threadIdx.x;
    const int wid  = tid >> 5;
    const int lane = tid & 31;
    const int g    = lane >> 2;
    const int t    = lane & 3;

    const int qt = blockIdx.x;
    const int h  = blockIdx.y;
    const int b  = blockIdx.z;
    const int qr0 = qt * 64 + wid * 16;      // this warp's first query row

    const size_t bh = (size_t)b*NH + h;
    const float* Qg = g_q + (bh*L + qt*64) * E;
    const float* Kg = g_k + bh*L*E;
    const float* Vg = g_v + bh*L*HS;

    // ---- stage Q tile (64x128) into Ks as tf32, then lift frags to regs ----
    #pragma unroll
    for (int i = 0; i < 16; i++) {
        const int f4  = tid + i * 128;
        const int row = f4 >> 5;
        const int c4  = f4 & 31;
        float4 q4 = *(const float4*)(Qg + (size_t)row * E + c4 * 4);
        *(uint4*)(Ks + row * KSTR + c4 * 4) =
            make_uint4(f2tf(q4.x), f2tf(q4.y), f2tf(q4.z), f2tf(q4.w));
    }
    __syncthreads();

    unsigned qa[16][4];
    #pragma unroll
    for (int ks = 0; ks < 16; ks++) {
        const int base = (wid * 16 + g) * KSTR + ks * 8 + t;
        qa[ks][0] = Ks[base];
        qa[ks][1] = Ks[base + 8 * KSTR];
        qa[ks][2] = Ks[base + 4];
        qa[ks][3] = Ks[base + 8 * KSTR + 4];
    }

    const float gulo = g_gu1[bh*L + qr0 + g];
    const float guhi = g_gu1[bh*L + qr0 + g + 8];
    const float* relLo = relpos + ((size_t)h*L + qr0 + g    ) * L;
    const float* relHi = relpos + ((size_t)h*L + qr0 + g + 8) * L;
    const float* mrow  = mask + (size_t)b * L;

    float m0 = -1e30f, m1 = -1e30f, l0 = 0.f, l1 = 0.f;
    float o[8][4];
    #pragma unroll
    for (int nt = 0; nt < 8; nt++)
        #pragma unroll
        for (int r = 0; r < 4; r++) o[nt][r] = 0.f;

    unsigned* Psw = Ps + wid * 16 * PSTRD;

    for (int kt = 0; kt < L/64; kt++) {
        const int kc0 = kt * 64;
        __syncthreads();   // Q-frag reads (iter 0) / V-frag reads done before overwrite

        // ---- load K tile (64x128) as tf32 ----
        #pragma unroll
        for (int i = 0; i < 16; i++) {
            const int f4  = tid + i * 128;
            const int row = f4 >> 5;
            const int c4  = f4 & 31;
            float4 k4 = *(const float4*)(Kg + (size_t)(kc0 + row) * E + c4 * 4);
            *(uint4*)(Ks + row * KSTR + c4 * 4) =
                make_uint4(f2tf(k4.x), f2tf(k4.y), f2tf(k4.z), f2tf(k4.w));
        }
        // ---- load V tile (64x64) transposed as tf32 ----
        #pragma unroll
        for (int i = 0; i < 8; i++) {
            const int f4 = tid + i * 128;
            const int kr = f4 >> 4;
            const int d0 = (f4 & 15) * 4;
            float4 v4 = *(const float4*)(Vg + (size_t)(kc0 + kr) * HS + d0);
            VsT[(d0+0) * VSTR + kr] = f2tf(v4.x);
            VsT[(d0+1) * VSTR + kr] = f2tf(v4.y);
            VsT[(d0+2) * VSTR + kr] = f2tf(v4.z);
            VsT[(d0+3) * VSTR + kr] = f2tf(v4.w);
        }
        __syncthreads();

        // ---- S = Q K^T (warp: 16 rows x 64 keys) ----
        float s[8][4];
        #pragma unroll
        for (int nt = 0; nt < 8; nt++)
            #pragma unroll
            for (int r = 0; r < 4; r++) s[nt][r] = 0.f;

        #pragma unroll
        for (int ks = 0; ks < 16; ks++) {
            unsigned bf[8][2];
            #pragma unroll
            for (int nt = 0; nt < 8; nt++) {
                const int r = (nt * 8 + g) * KSTR + ks * 8 + t;
                bf[nt][0] = Ks[r];
                bf[nt][1] = Ks[r + 4];
            }
            #pragma unroll
            for (int nt = 0; nt < 8; nt++)
                mma_tf32(s[nt], qa[ks], bf[nt]);
        }

        // ---- scale + mask + gated rel_pos ----
        #pragma unroll
        for (int nt = 0; nt < 8; nt++) {
            const int col = kc0 + nt * 8 + 2 * t;
            const float2 mk  = *(const float2*)(mrow  + col);
            const float2 rlo = *(const float2*)(relLo + col);
            const float2 rhi = *(const float2*)(relHi + col);
            s[nt][0] = fmaf(s[nt][0], 0.125f, fmaf(gulo, rlo.x, mk.x));
            s[nt][1] = fmaf(s[nt][1], 0.125f, fmaf(gulo, rlo.y, mk.y));
            s[nt][2] = fmaf(s[nt][2], 0.125f, fmaf(guhi, rhi.x, mk.x));
            s[nt][3] = fmaf(s[nt][3], 0.125f, fmaf(guhi, rhi.y, mk.y));
        }

        // ---- online softmax (rows g, g+8; reduce across quad lanes) ----
        float mx0 = -1e30f, mx1 = -1e30f;
        #pragma unroll
        for (int nt = 0; nt < 8; nt++) {
            mx0 = fmaxf(mx0, fmaxf(s[nt][0], s[nt][1]));
            mx1 = fmaxf(mx1, fmaxf(s[nt][2], s[nt][3]));
        }
        mx0 = fmaxf(mx0, __shfl_xor_sync(0xffffffffu, mx0, 1));
        mx0 = fmaxf(mx0, __shfl_xor_sync(0xffffffffu, mx0, 2));
        mx1 = fmaxf(mx1, __shfl_xor_sync(0xffffffffu, mx1, 1));
        mx1 = fmaxf(mx1, __shfl_xor_sync(0xffffffffu, mx1, 2));

        const float mn0 = fmaxf(m0, mx0);
        const float mn1 = fmaxf(m1, mx1);
        const float corr0 = __expf(m0 - mn0);
        const float corr1 = __expf(m1 - mn1);
        m0 = mn0; m1 = mn1;

        float rs0 = 0.f, rs1 = 0.f;
        #pragma unroll
        for (int nt = 0; nt < 8; nt++) {
            float p0 = __expf(s[nt][0] - mn0);
            float p1 = __expf(s[nt][1] - mn0);
            float p2 = __expf(s[nt][2] - mn1);
            float p3 = __expf(s[nt][3] - mn1);
            rs0 += p0 + p1;
            rs1 += p2 + p3;
            const int cc = nt * 8 + 2 * t;
            Psw[g * PSTRD + cc]           = f2tf(p0);
            Psw[g * PSTRD + cc + 1]       = f2tf(p1);
            Psw[(g + 8) * PSTRD + cc]     = f2tf(p2);
            Psw[(g + 8) * PSTRD + cc + 1] = f2tf(p3);
        }
        rs0 += __shfl_xor_sync(0xffffffffu, rs0, 1);
        rs0 += __shfl_xor_sync(0xffffffffu, rs0, 2);
        rs1 += __shfl_xor_sync(0xffffffffu, rs1, 1);
        rs1 += __shfl_xor_sync(0xffffffffu, rs1, 2);
        l0 = l0 * corr0 + rs0;
        l1 = l1 * corr1 + rs1;

        #pragma unroll
        for (int nt = 0; nt < 8; nt++) {
            o[nt][0] *= corr0; o[nt][1] *= corr0;
            o[nt][2] *= corr1; o[nt][3] *= corr1;
        }
        __syncwarp();

        // ---- O += P @ V ----
        #pragma unroll
        for (int ks = 0; ks < 8; ks++) {
            unsigned pa[4];
            pa[0] = Psw[g * PSTRD + ks * 8 + t];
            pa[1] = Psw[(g + 8) * PSTRD + ks * 8 + t];
            pa[2] = Psw[g * PSTRD + ks * 8 + t + 4];
            pa[3] = Psw[(g + 8) * PSTRD + ks * 8 + t + 4];
            #pragma unroll
            for (int nt = 0; nt < 8; nt++) {
                unsigned vb[2];
                const int r = (nt * 8 + g) * VSTR + ks * 8 + t;
                vb[0] = VsT[r];
                vb[1] = VsT[r + 4];
                mma_tf32(o[nt], pa, vb);
            }
        }
        __syncwarp();   // Psw reads done before next-iter overwrite
    }

    // ---- epilogue ----
    const float inv0 = 1.f / l0;
    const float inv1 = 1.f / l1;
    #pragma unroll
    for (int nt = 0; nt < 8; nt++) {
        const int d = h * HS + nt * 8 + 2 * t;
        float2 olo = make_float2(o[nt][0] * inv0, o[nt][1] * inv0);
        float2 ohi = make_float2(o[nt][2] * inv1, o[nt][3] * inv1);
        *(float2*)(out + ((size_t)b*L + qr0 + g    ) * HID + d) = olo;
        *(float2*)(out + ((size_t)b*L + qr0 + g + 8) * HID + d) = ohi;
    }
}

// ============================================================================
extern "C" void kernel_launch(void* const* d_in, const int* in_sizes, int n_in,
                              void* d_out, int out_size) {
    const float* hs   = (const float*)d_in[0];
    const float* mask = (const float*)d_in[1];
    const float* rel  = (const float*)d_in[2];
    const float* Wq   = (const float*)d_in[3];
    const float* bq   = (const float*)d_in[4];
    const float* Wk   = (const float*)d_in[5];
    const float* Wv   = (const float*)d_in[6];
    const float* bv   = (const float*)d_in[7];
    const float* Wg   = (const float*)d_in[8];
    const float* bg   = (const float*)d_in[9];
    const float* eco  = (const float*)d_in[10];
    float* out = (float*)d_out;

    // projections: Q (N=2048, bias), K (N=2048, no bias), V (N=1024, bias)
    proj_kernel<<<dim3(2048/128, ML/128), 128>>>(hs, Wq, bq,      E,  0);
    proj_kernel<<<dim3(2048/128, ML/128), 128>>>(hs, Wk, nullptr, E,  1);
    proj_kernel<<<dim3(1024/128, ML/128), 128>>>(hs, Wv, bv,      HS, 2);

    // gates
    gate_kernel<<<(B*NH*L)/8, 256>>>(Wg, bg, eco);

    // attention
    const int smem_bytes = (64*KSTR + HS*VSTR + 4*16*PSTRD) * (int)sizeof(unsigned);
    cudaFuncSetAttribute(attn_kernel,
                         cudaFuncAttributeMaxDynamicSharedMemorySize, smem_bytes);
    attn_kernel<<<dim3(L/64, NH, B), 128, smem_bytes>>>(mask, rel, out);
}

// round 16
// speedup vs baseline: 3.8808x; 1.0417x over previous
#include <cuda_runtime.h>
#include <math.h>

#define B   2
#define L   2048
#define HID 1024
#define NH  16
#define E   128
#define HS  64
#define ML  (B*L)          // 4096
#define KD  1024           // inner dim of projections

// ---------------- scratch (static device globals; no allocs allowed) -------
__device__ float g_q[B*NH*L*E];     // (b,h,l,e)
__device__ float g_k[B*NH*L*E];     // (b,h,l,e)
__device__ float g_v[B*NH*L*HS];    // (b,h,l,d)
__device__ float g_gu1[B*NH*L];     // gate_u_1 per (b,h,l)

// ---------------- tf32 helpers ---------------------------------------------
__device__ __forceinline__ unsigned f2tf(float x) {
    unsigned u;
    asm("cvt.rna.tf32.f32 %0, %1;" : "=r"(u) : "f"(x));
    return u;
}

__device__ __forceinline__ void mma_tf32(float* d, const unsigned* a, const unsigned* b) {
    asm volatile(
        "mma.sync.aligned.m16n8k8.row.col.f32.tf32.tf32.f32 "
        "{%0,%1,%2,%3}, {%4,%5,%6,%7}, {%8,%9}, {%0,%1,%2,%3};\n"
        : "+f"(d[0]), "+f"(d[1]), "+f"(d[2]), "+f"(d[3])
        : "r"(a[0]), "r"(a[1]), "r"(a[2]), "r"(a[3]), "r"(b[0]), "r"(b[1]));
}

// ============================================================================
// Projection GEMM (tf32 tensor cores):
//   C(ML x N) = A(ML x 1024) @ W^T(N x 1024) (+ bias), scatter to (B,NH,L,EG)
// Block tile 128x128, BK=32, 128 threads = 4 warps, warp tile 64x64.
// ============================================================================
#define PSTR 36   // smem k-stride (banks: (4g+t) mod 32 distinct -> conflict-free)

__global__ __launch_bounds__(128, 2) void proj_kernel(
    const float* __restrict__ A,
    const float* __restrict__ W,
    const float* __restrict__ bias,   // may be null
    int EG, int tgt)
{
    __shared__ unsigned As[128 * PSTR];
    __shared__ unsigned Ws[128 * PSTR];

    const int tid  = threadIdx.x;
    const int wid  = tid >> 5;
    const int lane = tid & 31;
    const int g    = lane >> 2;   // 0..7
    const int t    = lane & 3;    // 0..3
    const int wm   = wid >> 1;    // 0..1
    const int wn   = wid & 1;     // 0..1

    const int m0 = blockIdx.y * 128;
    const int n0 = blockIdx.x * 128;

    float c[4][8][4];
    #pragma unroll
    for (int mt = 0; mt < 4; mt++)
        #pragma unroll
        for (int nt = 0; nt < 8; nt++)
            #pragma unroll
            for (int r = 0; r < 4; r++) c[mt][nt][r] = 0.f;

    for (int k0 = 0; k0 < KD; k0 += 32) {
        __syncthreads();
        // load A,W tiles (128x32 each), convert to tf32, store to smem
        #pragma unroll
        for (int i = 0; i < 8; i++) {
            const int f4  = tid + i * 128;
            const int row = f4 >> 3;
            const int c4  = f4 & 7;
            float4 a4 = *(const float4*)(A + (size_t)(m0 + row) * KD + k0 + c4 * 4);
            float4 w4 = *(const float4*)(W + (size_t)(n0 + row) * KD + k0 + c4 * 4);
            uint4 au = make_uint4(f2tf(a4.x), f2tf(a4.y), f2tf(a4.z), f2tf(a4.w));
            uint4 wu = make_uint4(f2tf(w4.x), f2tf(w4.y), f2tf(w4.z), f2tf(w4.w));
            *(uint4*)(As + row * PSTR + c4 * 4) = au;
            *(uint4*)(Ws + row * PSTR + c4 * 4) = wu;
        }
        __syncthreads();

        #pragma unroll
        for (int ks = 0; ks < 4; ks++) {
            unsigned af[4][4], bf[8][2];
            #pragma unroll
            for (int mt = 0; mt < 4; mt++) {
                const int r = (wm * 64 + mt * 16 + g) * PSTR + ks * 8 + t;
                af[mt][0] = As[r];
                af[mt][1] = As[r + 8 * PSTR];
                af[mt][2] = As[r + 4];
                af[mt][3] = As[r + 8 * PSTR + 4];
            }
            #pragma unroll
            for (int nt = 0; nt < 8; nt++) {
                const int r = (wn * 64 + nt * 8 + g) * PSTR + ks * 8 + t;
                bf[nt][0] = Ws[r];
                bf[nt][1] = Ws[r + 4];
            }
            #pragma unroll
            for (int mt = 0; mt < 4; mt++)
                #pragma unroll
                for (int nt = 0; nt < 8; nt++)
                    mma_tf32(c[mt][nt], af[mt], bf[nt]);
        }
    }

    float* out = (tgt == 0) ? g_q : (tgt == 1) ? g_k : g_v;

    #pragma unroll
    for (int mt = 0; mt < 4; mt++) {
        #pragma unroll
        for (int rr = 0; rr < 2; rr++) {            // rr=0: row g, rr=1: row g+8
            const int mrow = m0 + wm * 64 + mt * 16 + g + rr * 8;
            const int bb = mrow / L;
            const int ll = mrow % L;
            #pragma unroll
            for (int nt = 0; nt < 8; nt++) {
                const int nn = n0 + wn * 64 + nt * 8 + 2 * t;
                const int h  = nn / EG;
                const int e  = nn % EG;
                float v0 = c[mt][nt][rr * 2 + 0];
                float v1 = c[mt][nt][rr * 2 + 1];
                if (bias) { v0 += bias[nn]; v1 += bias[nn + 1]; }
                float2 o = make_float2(v0, v1);
                *(float2*)(out + (((size_t)bb * NH + h) * L + ll) * EG + e) = o;
            }
        }
    }
}

// ============================================================================
// Gate: one warp per (b,h,l).
// ============================================================================
__global__ __launch_bounds__(256) void gate_kernel(
    const float* __restrict__ Wg,   // (8,128)
    const float* __restrict__ bg,   // (8)
    const float* __restrict__ eco)  // (NH)
{
    const int gw   = (blockIdx.x * blockDim.x + threadIdx.x) >> 5;
    const int lane = threadIdx.x & 31;
    if (gw >= B*NH*L) return;

    const float* qrow = g_q + (size_t)gw * E;
    float qv[4];
    #pragma unroll
    for (int i = 0; i < 4; i++) qv[i] = qrow[lane + 32*i];

    float d[8];
    #pragma unroll
    for (int j = 0; j < 8; j++) {
        float s = 0.f;
        #pragma unroll
        for (int i = 0; i < 4; i++)
            s = fmaf(qv[i], __ldg(&Wg[j*E + lane + 32*i]), s);
        #pragma unroll
        for (int off = 16; off; off >>= 1)
            s += __shfl_xor_sync(0xffffffffu, s, off);
        d[j] = s;
    }
    if (lane == 0) {
        float su = d[0]+d[1]+d[2]+d[3] + bg[0]+bg[1]+bg[2]+bg[3];
        float sr = d[4]+d[5]+d[6]+d[7] + bg[4]+bg[5]+bg[6]+bg[7];
        float gu = 1.f / (1.f + expf(-su));
        float gr = 1.f / (1.f + expf(-sr));
        const int h = (gw / L) % NH;
        g_gu1[gw] = fmaf(gu, fmaf(gr, eco[h], -1.f), 2.f);
    }
}

// ============================================================================
// Flash attention (tf32 tensor cores) with gated rel_pos bias.
// Block = (qtile 64, h, b), 128 threads = 4 warps, each warp: 16 full rows.
// Q frags register-resident. K / V^T / P staged in smem as tf32.
// ============================================================================
#define KSTR 132   // K/Q smem k-stride  ((4g+t) mod 32 distinct)
#define VSTR 68    // V^T smem stride
#define PSTRD 68   // P  smem stride

__global__ __launch_bounds__(128, 2) void attn_kernel(
    const float* __restrict__ mask,     // (B, L)
    const float* __restrict__ relpos,   // (NH, L, L)
    float* __restrict__ out)            // (B, L, HID)
{
    extern __shared__ unsigned sm[];
    unsigned* Ks  = sm;                    // [64][KSTR]  (also Q staging)
    unsigned* VsT = Ks + 64 * KSTR;        // [HS][VSTR]  (V transposed: [d][kr])
    unsigned* Ps  = VsT + HS * VSTR;       // [4][16][PSTRD]

    const int tid  = threadIdx.x;
    const int wid  = tid >> 5;
    const int lane = tid & 31;
    const int g    = lane >> 2;
    const int t    = lane & 3;

    const int qt = blockIdx.x;
    const int h  = blockIdx.y;
    const int b  = blockIdx.z;
    const int qr0 = qt * 64 + wid * 16;      // this warp's first query row

    const size_t bh = (size_t)b*NH + h;
    const float* Qg = g_q + (bh*L + qt*64) * E;
    const float* Kg = g_k + bh*L*E;
    const float* Vg = g_v + bh*L*HS;

    // ---- stage Q tile (64x128) into Ks as tf32, then lift frags to regs ----
    #pragma unroll
    for (int i = 0; i < 16; i++) {
        const int f4  = tid + i * 128;
        const int row = f4 >> 5;
        const int c4  = f4 & 31;
        float4 q4 = *(const float4*)(Qg + (size_t)row * E + c4 * 4);
        *(uint4*)(Ks + row * KSTR + c4 * 4) =
            make_uint4(f2tf(q4.x), f2tf(q4.y), f2tf(q4.z), f2tf(q4.w));
    }
    __syncthreads();

    unsigned qa[16][4];
    #pragma unroll
    for (int ks = 0; ks < 16; ks++) {
        const int base = (wid * 16 + g) * KSTR + ks * 8 + t;
        qa[ks][0] = Ks[base];
        qa[ks][1] = Ks[base + 8 * KSTR];
        qa[ks][2] = Ks[base + 4];
        qa[ks][3] = Ks[base + 8 * KSTR + 4];
    }

    const float gulo = g_gu1[bh*L + qr0 + g];
    const float guhi = g_gu1[bh*L + qr0 + g + 8];
    const float* relLo = relpos + ((size_t)h*L + qr0 + g    ) * L;
    const float* relHi = relpos + ((size_t)h*L + qr0 + g + 8) * L;
    const float* mrow  = mask + (size_t)b * L;

    float m0 = -1e30f, m1 = -1e30f, l0 = 0.f, l1 = 0.f;
    float o[8][4];
    #pragma unroll
    for (int nt = 0; nt < 8; nt++)
        #pragma unroll
        for (int r = 0; r < 4; r++) o[nt][r] = 0.f;

    unsigned* Psw = Ps + wid * 16 * PSTRD;

    for (int kt = 0; kt < L/64; kt++) {
        const int kc0 = kt * 64;
        __syncthreads();   // Q-frag reads (iter 0) / V-frag reads done before overwrite

        // ---- load K tile (64x128) as tf32 ----
        #pragma unroll
        for (int i = 0; i < 16; i++) {
            const int f4  = tid + i * 128;
            const int row = f4 >> 5;
            const int c4  = f4 & 31;
            float4 k4 = *(const float4*)(Kg + (size_t)(kc0 + row) * E + c4 * 4);
            *(uint4*)(Ks + row * KSTR + c4 * 4) =
                make_uint4(f2tf(k4.x), f2tf(k4.y), f2tf(k4.z), f2tf(k4.w));
        }
        // ---- load V tile (64x64) transposed as tf32 ----
        #pragma unroll
        for (int i = 0; i < 8; i++) {
            const int f4 = tid + i * 128;
            const int kr = f4 >> 4;
            const int d0 = (f4 & 15) * 4;
            float4 v4 = *(const float4*)(Vg + (size_t)(kc0 + kr) * HS + d0);
            VsT[(d0+0) * VSTR + kr] = f2tf(v4.x);
            VsT[(d0+1) * VSTR + kr] = f2tf(v4.y);
            VsT[(d0+2) * VSTR + kr] = f2tf(v4.z);
            VsT[(d0+3) * VSTR + kr] = f2tf(v4.w);
        }
        __syncthreads();

        // ---- S = Q K^T (warp: 16 rows x 64 keys) ----
        float s[8][4];
        #pragma unroll
        for (int nt = 0; nt < 8; nt++)
            #pragma unroll
            for (int r = 0; r < 4; r++) s[nt][r] = 0.f;

        #pragma unroll
        for (int ks = 0; ks < 16; ks++) {
            unsigned bf[8][2];
            #pragma unroll
            for (int nt = 0; nt < 8; nt++) {
                const int r = (nt * 8 + g) * KSTR + ks * 8 + t;
                bf[nt][0] = Ks[r];
                bf[nt][1] = Ks[r + 4];
            }
            #pragma unroll
            for (int nt = 0; nt < 8; nt++)
                mma_tf32(s[nt], qa[ks], bf[nt]);
        }

        // ---- scale + mask + gated rel_pos ----
        #pragma unroll
        for (int nt = 0; nt < 8; nt++) {
            const int col = kc0 + nt * 8 + 2 * t;
            const float2 mk  = *(const float2*)(mrow  + col);
            const float2 rlo = *(const float2*)(relLo + col);
            const float2 rhi = *(const float2*)(relHi + col);
            s[nt][0] = fmaf(s[nt][0], 0.125f, fmaf(gulo, rlo.x, mk.x));
            s[nt][1] = fmaf(s[nt][1], 0.125f, fmaf(gulo, rlo.y, mk.y));
            s[nt][2] = fmaf(s[nt][2], 0.125f, fmaf(guhi, rhi.x, mk.x));
            s[nt][3] = fmaf(s[nt][3], 0.125f, fmaf(guhi, rhi.y, mk.y));
        }

        // ---- online softmax (rows g, g+8; reduce across quad lanes) ----
        float mx0 = -1e30f, mx1 = -1e30f;
        #pragma unroll
        for (int nt = 0; nt < 8; nt++) {
            mx0 = fmaxf(mx0, fmaxf(s[nt][0], s[nt][1]));
            mx1 = fmaxf(mx1, fmaxf(s[nt][2], s[nt][3]));
        }
        mx0 = fmaxf(mx0, __shfl_xor_sync(0xffffffffu, mx0, 1));
        mx0 = fmaxf(mx0, __shfl_xor_sync(0xffffffffu, mx0, 2));
        mx1 = fmaxf(mx1, __shfl_xor_sync(0xffffffffu, mx1, 1));
        mx1 = fmaxf(mx1, __shfl_xor_sync(0xffffffffu, mx1, 2));

        const float mn0 = fmaxf(m0, mx0);
        const float mn1 = fmaxf(m1, mx1);
        const float corr0 = __expf(m0 - mn0);
        const float corr1 = __expf(m1 - mn1);
        m0 = mn0; m1 = mn1;

        float rs0 = 0.f, rs1 = 0.f;
        #pragma unroll
        for (int nt = 0; nt < 8; nt++) {
            float p0 = __expf(s[nt][0] - mn0);
            float p1 = __expf(s[nt][1] - mn0);
            float p2 = __expf(s[nt][2] - mn1);
            float p3 = __expf(s[nt][3] - mn1);
            rs0 += p0 + p1;
            rs1 += p2 + p3;
            const int cc = nt * 8 + 2 * t;
            Psw[g * PSTRD + cc]           = f2tf(p0);
            Psw[g * PSTRD + cc + 1]       = f2tf(p1);
            Psw[(g + 8) * PSTRD + cc]     = f2tf(p2);
            Psw[(g + 8) * PSTRD + cc + 1] = f2tf(p3);
        }
        rs0 += __shfl_xor_sync(0xffffffffu, rs0, 1);
        rs0 += __shfl_xor_sync(0xffffffffu, rs0, 2);
        rs1 += __shfl_xor_sync(0xffffffffu, rs1, 1);
        rs1 += __shfl_xor_sync(0xffffffffu, rs1, 2);
        l0 = l0 * corr0 + rs0;
        l1 = l1 * corr1 + rs1;

        #pragma unroll
        for (int nt = 0; nt < 8; nt++) {
            o[nt][0] *= corr0; o[nt][1] *= corr0;
            o[nt][2] *= corr1; o[nt][3] *= corr1;
        }
        __syncwarp();

        // ---- O += P @ V ----
        #pragma unroll
        for (int ks = 0; ks < 8; ks++) {
            unsigned pa[4];
            pa[0] = Psw[g * PSTRD + ks * 8 + t];
            pa[1] = Psw[(g + 8) * PSTRD + ks * 8 + t];
            pa[2] = Psw[g * PSTRD + ks * 8 + t + 4];
            pa[3] = Psw[(g + 8) * PSTRD + ks * 8 + t + 4];
            #pragma unroll
            for (int nt = 0; nt < 8; nt++) {
                unsigned vb[2];
                const int r = (nt * 8 + g) * VSTR + ks * 8 + t;
                vb[0] = VsT[r];
                vb[1] = VsT[r + 4];
                mma_tf32(o[nt], pa, vb);
            }
        }
        __syncwarp();   // Psw reads done before next-iter overwrite
    }

    // ---- epilogue ----
    const float inv0 = 1.f / l0;
    const float inv1 = 1.f / l1;
    #pragma unroll
    for (int nt = 0; nt < 8; nt++) {
        const int d = h * HS + nt * 8 + 2 * t;
        float2 olo = make_float2(o[nt][0] * inv0, o[nt][1] * inv0);
        float2 ohi = make_float2(o[nt][2] * inv1, o[nt][3] * inv1);
        *(float2*)(out + ((size_t)b*L + qr0 + g    ) * HID + d) = olo;
        *(float2*)(out + ((size_t)b*L + qr0 + g + 8) * HID + d) = ohi;
    }
}

// ============================================================================
extern "C" void kernel_launch(void* const* d_in, const int* in_sizes, int n_in,
                              void* d_out, int out_size) {
    const float* hs   = (const float*)d_in[0];
    const float* mask = (const float*)d_in[1];
    const float* rel  = (const float*)d_in[2];
    const float* Wq   = (const float*)d_in[3];
    const float* bq   = (const float*)d_in[4];
    const float* Wk   = (const float*)d_in[5];
    const float* Wv   = (const float*)d_in[6];
    const float* bv   = (const float*)d_in[7];
    const float* Wg   = (const float*)d_in[8];
    const float* bg   = (const float*)d_in[9];
    const float* eco  = (const float*)d_in[10];
    float* out = (float*)d_out;

    // projections: Q (N=2048, bias), K (N=2048, no bias), V (N=1024, bias)
    proj_kernel<<<dim3(2048/128, ML/128), 128>>>(hs, Wq, bq,      E,  0);
    proj_kernel<<<dim3(2048/128, ML/128), 128>>>(hs, Wk, nullptr, E,  1);
    proj_kernel<<<dim3(1024/128, ML/128), 128>>>(hs, Wv, bv,      HS, 2);

    // gates
    gate_kernel<<<(B*NH*L)/8, 256>>>(Wg, bg, eco);

    // attention
    const int smem_bytes = (64*KSTR + HS*VSTR + 4*16*PSTRD) * (int)sizeof(unsigned);
    cudaFuncSetAttribute(attn_kernel,
                         cudaFuncAttributeMaxDynamicSharedMemorySize, smem_bytes);
    attn_kernel<<<dim3(L/64, NH, B), 128, smem_bytes>>>(mask, rel, out);
}

// round 17
// speedup vs baseline: 3.8846x; 1.0010x over previous
#include <cuda_runtime.h>
#include <math.h>

#define B   2
#define L   2048
#define HID 1024
#define NH  16
#define E   128
#define HS  64
#define ML  (B*L)          // 4096
#define KD  1024           // inner dim of projections

// ---------------- scratch (static device globals; no allocs allowed) -------
__device__ float g_q[B*NH*L*E];     // (b,h,l,e)
__device__ float g_k[B*NH*L*E];     // (b,h,l,e)
__device__ float g_v[B*NH*L*HS];    // (b,h,l,d)
__device__ float g_gu1[B*NH*L];     // gate_u_1 per (b,h,l)

// ---------------- tf32 helpers ---------------------------------------------
__device__ __forceinline__ unsigned f2tf(float x) {
    unsigned u;
    asm("cvt.rna.tf32.f32 %0, %1;" : "=r"(u) : "f"(x));
    return u;
}

__device__ __forceinline__ void mma_tf32(float* d, const unsigned* a, const unsigned* b) {
    asm volatile(
        "mma.sync.aligned.m16n8k8.row.col.f32.tf32.tf32.f32 "
        "{%0,%1,%2,%3}, {%4,%5,%6,%7}, {%8,%9}, {%0,%1,%2,%3};\n"
        : "+f"(d[0]), "+f"(d[1]), "+f"(d[2]), "+f"(d[3])
        : "r"(a[0]), "r"(a[1]), "r"(a[2]), "r"(a[3]), "r"(b[0]), "r"(b[1]));
}

// ============================================================================
// Projection GEMM (tf32 tensor cores):
//   C(ML x N) = A(ML x 1024) @ W^T(N x 1024) (+ bias), scatter to (B,NH,L,EG)
// Block tile 128x128, BK=32, 128 threads = 4 warps, warp tile 64x64.
// ============================================================================
#define PSTR 36   // smem k-stride (banks: (4g+t) mod 32 distinct -> conflict-free)

__global__ __launch_bounds__(128, 2) void proj_kernel(
    const float* __restrict__ A,
    const float* __restrict__ W,
    const float* __restrict__ bias,   // may be null
    int EG, int tgt)
{
    __shared__ unsigned As[128 * PSTR];
    __shared__ unsigned Ws[128 * PSTR];

    const int tid  = threadIdx.x;
    const int wid  = tid >> 5;
    const int lane = tid & 31;
    const int g    = lane >> 2;   // 0..7
    const int t    = lane & 3;    // 0..3
    const int wm   = wid >> 1;    // 0..1
    const int wn   = wid & 1;     // 0..1

    const int m0 = blockIdx.y * 128;
    const int n0 = blockIdx.x * 128;

    float c[4][8][4];
    #pragma unroll
    for (int mt = 0; mt < 4; mt++)
        #pragma unroll
        for (int nt = 0; nt < 8; nt++)
            #pragma unroll
            for (int r = 0; r < 4; r++) c[mt][nt][r] = 0.f;

    for (int k0 = 0; k0 < KD; k0 += 32) {
        __syncthreads();
        // load A,W tiles (128x32 each), convert to tf32, store to smem
        #pragma unroll
        for (int i = 0; i < 8; i++) {
            const int f4  = tid + i * 128;
            const int row = f4 >> 3;
            const int c4  = f4 & 7;
            float4 a4 = *(const float4*)(A + (size_t)(m0 + row) * KD + k0 + c4 * 4);
            float4 w4 = *(const float4*)(W + (size_t)(n0 + row) * KD + k0 + c4 * 4);
            uint4 au = make_uint4(f2tf(a4.x), f2tf(a4.y), f2tf(a4.z), f2tf(a4.w));
            uint4 wu = make_uint4(f2tf(w4.x), f2tf(w4.y), f2tf(w4.z), f2tf(w4.w));
            *(uint4*)(As + row * PSTR + c4 * 4) = au;
            *(uint4*)(Ws + row * PSTR + c4 * 4) = wu;
        }
        __syncthreads();

        #pragma unroll
        for (int ks = 0; ks < 4; ks++) {
            unsigned af[4][4], bf[8][2];
            #pragma unroll
            for (int mt = 0; mt < 4; mt++) {
                const int r = (wm * 64 + mt * 16 + g) * PSTR + ks * 8 + t;
                af[mt][0] = As[r];
                af[mt][1] = As[r + 8 * PSTR];
                af[mt][2] = As[r + 4];
                af[mt][3] = As[r + 8 * PSTR + 4];
            }
            #pragma unroll
            for (int nt = 0; nt < 8; nt++) {
                const int r = (wn * 64 + nt * 8 + g) * PSTR + ks * 8 + t;
                bf[nt][0] = Ws[r];
                bf[nt][1] = Ws[r + 4];
            }
            #pragma unroll
            for (int mt = 0; mt < 4; mt++)
                #pragma unroll
                for (int nt = 0; nt < 8; nt++)
                    mma_tf32(c[mt][nt], af[mt], bf[nt]);
        }
    }

    float* out = (tgt == 0) ? g_q : (tgt == 1) ? g_k : g_v;

    #pragma unroll
    for (int mt = 0; mt < 4; mt++) {
        #pragma unroll
        for (int rr = 0; rr < 2; rr++) {            // rr=0: row g, rr=1: row g+8
            const int mrow = m0 + wm * 64 + mt * 16 + g + rr * 8;
            const int bb = mrow / L;
            const int ll = mrow % L;
            #pragma unroll
            for (int nt = 0; nt < 8; nt++) {
                const int nn = n0 + wn * 64 + nt * 8 + 2 * t;
                const int h  = nn / EG;
                const int e  = nn % EG;
                float v0 = c[mt][nt][rr * 2 + 0];
                float v1 = c[mt][nt][rr * 2 + 1];
                if (bias) { v0 += bias[nn]; v1 += bias[nn + 1]; }
                float2 o = make_float2(v0, v1);
                *(float2*)(out + (((size_t)bb * NH + h) * L + ll) * EG + e) = o;
            }
        }
    }
}

// ============================================================================
// Gate: one warp per (b,h,l).
// ============================================================================
__global__ __launch_bounds__(256) void gate_kernel(
    const float* __restrict__ Wg,   // (8,128)
    const float* __restrict__ bg,   // (8)
    const float* __restrict__ eco)  // (NH)
{
    const int gw   = (blockIdx.x * blockDim.x + threadIdx.x) >> 5;
    const int lane = threadIdx.x & 31;
    if (gw >= B*NH*L) return;

    const float* qrow = g_q + (size_t)gw * E;
    float qv[4];
    #pragma unroll
    for (int i = 0; i < 4; i++) qv[i] = qrow[lane + 32*i];

    float d[8];
    #pragma unroll
    for (int j = 0; j < 8; j++) {
        float s = 0.f;
        #pragma unroll
        for (int i = 0; i < 4; i++)
            s = fmaf(qv[i], __ldg(&Wg[j*E + lane + 32*i]), s);
        #pragma unroll
        for (int off = 16; off; off >>= 1)
            s += __shfl_xor_sync(0xffffffffu, s, off);
        d[j] = s;
    }
    if (lane == 0) {
        float su = d[0]+d[1]+d[2]+d[3] + bg[0]+bg[1]+bg[2]+bg[3];
        float sr = d[4]+d[5]+d[6]+d[7] + bg[4]+bg[5]+bg[6]+bg[7];
        float gu = 1.f / (1.f + expf(-su));
        float gr = 1.f / (1.f + expf(-sr));
        const int h = (gw / L) % NH;
        g_gu1[gw] = fmaf(gu, fmaf(gr, eco[h], -1.f), 2.f);
    }
}

// ============================================================================
// Flash attention (tf32 tensor cores) with gated rel_pos bias.
// Block = (qtile 64, h, b), 128 threads = 4 warps, each warp: 16 full rows.
// Q frags register-resident. K / V^T / P staged in smem as tf32.
// ============================================================================
#define KSTR 132   // K/Q smem k-stride  ((4g+t) mod 32 distinct)
#define VSTR 68    // V^T smem stride
#define PSTRD 68   // P  smem stride

__global__ __launch_bounds__(128, 2) void attn_kernel(
    const float* __restrict__ mask,     // (B, L)
    const float* __restrict__ relpos,   // (NH, L, L)
    float* __restrict__ out)            // (B, L, HID)
{
    extern __shared__ unsigned sm[];
    unsigned* Ks  = sm;                    // [64][KSTR]  (also Q staging)
    unsigned* VsT = Ks + 64 * KSTR;        // [HS][VSTR]  (V transposed: [d][kr])
    unsigned* Ps  = VsT + HS * VSTR;       // [4][16][PSTRD]

    const int tid  = threadIdx.x;
    const int wid  = tid >> 5;
    const int lane = tid & 31;
    const int g    = lane >> 2;
    const int t    = lane & 3;

    const int qt = blockIdx.x;
    const int h  = blockIdx.y;
    const int b  = blockIdx.z;
    const int qr0 = qt * 64 + wid * 16;      // this warp's first query row

    const size_t bh = (size_t)b*NH + h;
    const float* Qg = g_q + (bh*L + qt*64) * E;
    const float* Kg = g_k + bh*L*E;
    const float* Vg = g_v + bh*L*HS;

    // ---- stage Q tile (64x128) into Ks as tf32, then lift frags to regs ----
    #pragma unroll
    for (int i = 0; i < 16; i++) {
        const int f4  = tid + i * 128;
        const int row = f4 >> 5;
        const int c4  = f4 & 31;
        float4 q4 = *(const float4*)(Qg + (size_t)row * E + c4 * 4);
        *(uint4*)(Ks + row * KSTR + c4 * 4) =
            make_uint4(f2tf(q4.x), f2tf(q4.y), f2tf(q4.z), f2tf(q4.w));
    }
    __syncthreads();

    unsigned qa[16][4];
    #pragma unroll
    for (int ks = 0; ks < 16; ks++) {
        const int base = (wid * 16 + g) * KSTR + ks * 8 + t;
        qa[ks][0] = Ks[base];
        qa[ks][1] = Ks[base + 8 * KSTR];
        qa[ks][2] = Ks[base + 4];
        qa[ks][3] = Ks[base + 8 * KSTR + 4];
    }

    const float gulo = g_gu1[bh*L + qr0 + g];
    const float guhi = g_gu1[bh*L + qr0 + g + 8];
    const float* relLo = relpos + ((size_t)h*L + qr0 + g    ) * L;
    const float* relHi = relpos + ((size_t)h*L + qr0 + g + 8) * L;
    const float* mrow  = mask + (size_t)b * L;

    float m0 = -1e30f, m1 = -1e30f, l0 = 0.f, l1 = 0.f;
    float o[8][4];
    #pragma unroll
    for (int nt = 0; nt < 8; nt++)
        #pragma unroll
        for (int r = 0; r < 4; r++) o[nt][r] = 0.f;

    unsigned* Psw = Ps + wid * 16 * PSTRD;

    for (int kt = 0; kt < L/64; kt++) {
        const int kc0 = kt * 64;
        __syncthreads();   // Q-frag reads (iter 0) / V-frag reads done before overwrite

        // ---- load K tile (64x128) as tf32 ----
        #pragma unroll
        for (int i = 0; i < 16; i++) {
            const int f4  = tid + i * 128;
            const int row = f4 >> 5;
            const int c4  = f4 & 31;
            float4 k4 = *(const float4*)(Kg + (size_t)(kc0 + row) * E + c4 * 4);
            *(uint4*)(Ks + row * KSTR + c4 * 4) =
                make_uint4(f2tf(k4.x), f2tf(k4.y), f2tf(k4.z), f2tf(k4.w));
        }
        // ---- load V tile (64x64) transposed as tf32 ----
        #pragma unroll
        for (int i = 0; i < 8; i++) {
            const int f4 = tid + i * 128;
            const int kr = f4 >> 4;
            const int d0 = (f4 & 15) * 4;
            float4 v4 = *(const float4*)(Vg + (size_t)(kc0 + kr) * HS + d0);
            VsT[(d0+0) * VSTR + kr] = f2tf(v4.x);
            VsT[(d0+1) * VSTR + kr] = f2tf(v4.y);
            VsT[(d0+2) * VSTR + kr] = f2tf(v4.z);
            VsT[(d0+3) * VSTR + kr] = f2tf(v4.w);
        }
        __syncthreads();

        // ---- S = Q K^T (warp: 16 rows x 64 keys) ----
        float s[8][4];
        #pragma unroll
        for (int nt = 0; nt < 8; nt++)
            #pragma unroll
            for (int r = 0; r < 4; r++) s[nt][r] = 0.f;

        #pragma unroll
        for (int ks = 0; ks < 16; ks++) {
            unsigned bf[8][2];
            #pragma unroll
            for (int nt = 0; nt < 8; nt++) {
                const int r = (nt * 8 + g) * KSTR + ks * 8 + t;
                bf[nt][0] = Ks[r];
                bf[nt][1] = Ks[r + 4];
            }
            #pragma unroll
            for (int nt = 0; nt < 8; nt++)
                mma_tf32(s[nt], qa[ks], bf[nt]);
        }

        // ---- scale + mask + gated rel_pos ----
        #pragma unroll
        for (int nt = 0; nt < 8; nt++) {
            const int col = kc0 + nt * 8 + 2 * t;
            const float2 mk  = *(const float2*)(mrow  + col);
            const float2 rlo = *(const float2*)(relLo + col);
            const float2 rhi = *(const float2*)(relHi + col);
            s[nt][0] = fmaf(s[nt][0], 0.125f, fmaf(gulo, rlo.x, mk.x));
            s[nt][1] = fmaf(s[nt][1], 0.125f, fmaf(gulo, rlo.y, mk.y));
            s[nt][2] = fmaf(s[nt][2], 0.125f, fmaf(guhi, rhi.x, mk.x));
            s[nt][3] = fmaf(s[nt][3], 0.125f, fmaf(guhi, rhi.y, mk.y));
        }

        // ---- online softmax (rows g, g+8; reduce across quad lanes) ----
        float mx0 = -1e30f, mx1 = -1e30f;
        #pragma unroll
        for (int nt = 0; nt < 8; nt++) {
            mx0 = fmaxf(mx0, fmaxf(s[nt][0], s[nt][1]));
            mx1 = fmaxf(mx1, fmaxf(s[nt][2], s[nt][3]));
        }
        mx0 = fmaxf(mx0, __shfl_xor_sync(0xffffffffu, mx0, 1));
        mx0 = fmaxf(mx0, __shfl_xor_sync(0xffffffffu, mx0, 2));
        mx1 = fmaxf(mx1, __shfl_xor_sync(0xffffffffu, mx1, 1));
        mx1 = fmaxf(mx1, __shfl_xor_sync(0xffffffffu, mx1, 2));

        const float mn0 = fmaxf(m0, mx0);
        const float mn1 = fmaxf(m1, mx1);
        const float corr0 = __expf(m0 - mn0);
        const float corr1 = __expf(m1 - mn1);
        m0 = mn0; m1 = mn1;

        float rs0 = 0.f, rs1 = 0.f;
        #pragma unroll
        for (int nt = 0; nt < 8; nt++) {
            float p0 = __expf(s[nt][0] - mn0);
            float p1 = __expf(s[nt][1] - mn0);
            float p2 = __expf(s[nt][2] - mn1);
            float p3 = __expf(s[nt][3] - mn1);
            rs0 += p0 + p1;
            rs1 += p2 + p3;
            const int cc = nt * 8 + 2 * t;
            Psw[g * PSTRD + cc]           = f2tf(p0);
            Psw[g * PSTRD + cc + 1]       = f2tf(p1);
            Psw[(g + 8) * PSTRD + cc]     = f2tf(p2);
            Psw[(g + 8) * PSTRD + cc + 1] = f2tf(p3);
        }
        rs0 += __shfl_xor_sync(0xffffffffu, rs0, 1);
        rs0 += __shfl_xor_sync(0xffffffffu, rs0, 2);
        rs1 += __shfl_xor_sync(0xffffffffu, rs1, 1);
        rs1 += __shfl_xor_sync(0xffffffffu, rs1, 2);
        l0 = l0 * corr0 + rs0;
        l1 = l1 * corr1 + rs1;

        #pragma unroll
        for (int nt = 0; nt < 8; nt++) {
            o[nt][0] *= corr0; o[nt][1] *= corr0;
            o[nt][2] *= corr1; o[nt][3] *= corr1;
        }
        __syncwarp();

        // ---- O += P @ V ----
        #pragma unroll
        for (int ks = 0; ks < 8; ks++) {
            unsigned pa[4];
            pa[0] = Psw[g * PSTRD + ks * 8 + t];
            pa[1] = Psw[(g + 8) * PSTRD + ks * 8 + t];
            pa[2] = Psw[g * PSTRD + ks * 8 + t + 4];
            pa[3] = Psw[(g + 8) * PSTRD + ks * 8 + t + 4];
            #pragma unroll
            for (int nt = 0; nt < 8; nt++) {
                unsigned vb[2];
                const int r = (nt * 8 + g) * VSTR + ks * 8 + t;
                vb[0] = VsT[r];
                vb[1] = VsT[r + 4];
                mma_tf32(o[nt], pa, vb);
            }
        }
        __syncwarp();   // Psw reads done before next-iter overwrite
    }

    // ---- epilogue ----
    const float inv0 = 1.f / l0;
    const float inv1 = 1.f / l1;
    #pragma unroll
    for (int nt = 0; nt < 8; nt++) {
        const int d = h * HS + nt * 8 + 2 * t;
        float2 olo = make_float2(o[nt][0] * inv0, o[nt][1] * inv0);
        float2 ohi = make_float2(o[nt][2] * inv1, o[nt][3] * inv1);
        *(float2*)(out + ((size_t)b*L + qr0 + g    ) * HID + d) = olo;
        *(float2*)(out + ((size_t)b*L + qr0 + g + 8) * HID + d) = ohi;
    }
}

// ============================================================================
extern "C" void kernel_launch(void* const* d_in, const int* in_sizes, int n_in,
                              void* d_out, int out_size) {
    const float* hs   = (const float*)d_in[0];
    const float* mask = (const float*)d_in[1];
    const float* rel  = (const float*)d_in[2];
    const float* Wq   = (const float*)d_in[3];
    const float* bq   = (const float*)d_in[4];
    const float* Wk   = (const float*)d_in[5];
    const float* Wv   = (const float*)d_in[6];
    const float* bv   = (const float*)d_in[7];
    const float* Wg   = (const float*)d_in[8];
    const float* bg   = (const float*)d_in[9];
    const float* eco  = (const float*)d_in[10];
    float* out = (float*)d_out;

    // projections: Q (N=2048, bias), K (N=2048, no bias), V (N=1024, bias)
    proj_kernel<<<dim3(2048/128, ML/128), 128>>>(hs, Wq, bq,      E,  0);
    proj_kernel<<<dim3(2048/128, ML/128), 128>>>(hs, Wk, nullptr, E,  1);
    proj_kernel<<<dim3(1024/128, ML/128), 128>>>(hs, Wv, bv,      HS, 2);

    // gates
    gate_kernel<<<(B*NH*L)/8, 256>>>(Wg, bg, eco);

    // attention
    const int smem_bytes = (64*KSTR + HS*VSTR + 4*16*PSTRD) * (int)sizeof(unsigned);
    cudaFuncSetAttribute(attn_kernel,
                         cudaFuncAttributeMaxDynamicSharedMemorySize, smem_bytes);
    attn_kernel<<<dim3(L/64, NH, B), 128, smem_bytes>>>(mask, rel, out);
}